// round 6
// baseline (speedup 1.0000x reference)
#include <cuda_runtime.h>
#include <cuda_fp16.h>
#include <cstdint>

#define N_NODES 100000
#define HALFN   50000
#define QN      25000
#define KK 5
#define CC 16
#define EE 3200000
#define PPK (EE / 4)              // 800,000 int4-packs per k
#define NT 1024
#define CTAS_PER_K 28             // 28 CTAs (14 clusters) per k -> 140 CTAs total

// smem: [0,100000) fp16 half-slice (50K nodes), [100000,200000) fp32 acc (25K rows)
#define OFF_ACC 100000
#define SMEM_TOTAL 200000

__device__ __half g_Zt[KK * N_NODES];

__device__ __forceinline__ uint32_t s2u(const void* p) {
    uint32_t a;
    asm("{ .reg .u64 t; cvta.to.shared.u64 t, %1; cvt.u32.u64 %0, t; }" : "=r"(a) : "l"(p));
    return a;
}

// Kernel 1: Z = X @ h (k-major fp16), zero y.
__global__ __launch_bounds__(256) void compute_z_kernel(
    const float* __restrict__ X, const float* __restrict__ h, float* __restrict__ y)
{
    __shared__ float hs[CC * KK];
    if (threadIdx.x < CC * KK) hs[threadIdx.x] = h[threadIdx.x];
    __syncthreads();
    int n = blockIdx.x * blockDim.x + threadIdx.x;
    if (n >= N_NODES) return;
    float x[CC];
    const float4* xp = reinterpret_cast<const float4*>(X + (size_t)n * CC);
#pragma unroll
    for (int i = 0; i < CC / 4; i++) {
        float4 v = xp[i];
        x[4*i+0]=v.x; x[4*i+1]=v.y; x[4*i+2]=v.z; x[4*i+3]=v.w;
    }
#pragma unroll
    for (int k = 0; k < KK; k++) {
        float acc = 0.f;
#pragma unroll
        for (int c = 0; c < CC; c++) acc += x[c] * hs[c * KK + k];
        g_Zt[k * N_NODES + n] = __float2half_rn(acc);
    }
    y[n] = 0.f;
}

__device__ __forceinline__ float gather_z(uint32_t zbase, int c) {
    uint32_t rk  = (uint32_t)(c >= HALFN);
    uint32_t la  = zbase + (uint32_t)(c - (int)rk * HALFN) * 2u;
    uint32_t ra;
    asm("mapa.shared::cluster.u32 %0, %1, %2;" : "=r"(ra) : "r"(la), "r"(rk));
    unsigned short hb;
    asm volatile("ld.shared::cluster.u16 %0, [%1];" : "=h"(hb) : "r"(ra));
    return __half2float(__ushort_as_half(hb));
}

__device__ __forceinline__ void scatter_add(uint32_t accbase, float* y, int r, float s) {
    uint32_t rk = (uint32_t)(r >= QN && r < HALFN);
    uint32_t la = accbase + (uint32_t)(r - (int)rk * QN) * 4u;
    uint32_t sa;
    asm("mapa.shared::cluster.u32 %0, %1, %2;" : "=r"(sa) : "r"(la), "r"(rk));
    // Predicated dual-pipe dispatch: no branch, no BSSY.
    asm volatile(
        "{\n\t.reg .pred p;\n\t"
        "setp.lt.s32 p, %0, 50000;\n\t"
        "@p  red.shared::cluster.add.f32 [%1], %3;\n\t"
        "@!p red.global.add.f32 [%2], %3;\n\t}"
        :: "r"(r), "r"(sa), "l"(y + r), "f"(s) : "memory");
}

// Kernel 2: 2-CTA cluster. Each CTA: 100KB fp16 half-slice + 100KB fp32 acc.
// Atomics split across shared crossbar (rows<50K) and L1tex/REDG (rows>=50K).
__global__ __launch_bounds__(NT, 1) __cluster_dims__(2, 1, 1)
void scatter_kernel(const int4* __restrict__ rows, const int4* __restrict__ cols,
                    const float4* __restrict__ vals, float* __restrict__ y)
{
    extern __shared__ __align__(16) char smem[];
    __half* sZ   = reinterpret_cast<__half*>(smem);
    float*  sAcc = reinterpret_cast<float*>(smem + OFF_ACC);
    const uint32_t sbase   = s2u(smem);
    const uint32_t accbase = sbase + OFF_ACC;
    const int tid = threadIdx.x;

    uint32_t rank;
    asm("mov.u32 %0, %%cluster_ctarank;" : "=r"(rank));
    const int k = blockIdx.y;

    // Stage my half of slice k: nodes [rank*50K, rank*50K+50K)
    {
        const int4* src = reinterpret_cast<const int4*>(g_Zt + (size_t)k * N_NODES + rank * HALFN);
        int4* dst = reinterpret_cast<int4*>(sZ);
        for (int i = tid; i < HALFN * 2 / 16; i += NT) dst[i] = src[i];
        float4* a4 = reinterpret_cast<float4*>(sAcc);
        float4 z4 = make_float4(0.f, 0.f, 0.f, 0.f);
        for (int i = tid; i < QN / 4; i += NT) a4[i] = z4;
    }
    // Cluster barrier: both CTAs' smem staged before any remote access.
    asm volatile("barrier.cluster.arrive.aligned;" ::: "memory");
    asm volatile("barrier.cluster.wait.aligned;" ::: "memory");

    // Pack range for this CTA within k.
    int cik = blockIdx.x;                                  // 0..27
    int p   = (int)(((long long)cik * PPK) / CTAS_PER_K) + k * PPK;
    int end = (int)(((long long)(cik + 1) * PPK) / CTAS_PER_K) + k * PPK;

    for (int q = p + tid; q < end; q += NT) {
        int4   r = __ldcg(rows + q);
        int4   c = __ldcg(cols + q);
        float4 v = __ldcg(vals + q);

        float z0 = gather_z(sbase, c.x);
        float z1 = gather_z(sbase, c.y);
        float z2 = gather_z(sbase, c.z);
        float z3 = gather_z(sbase, c.w);

        scatter_add(accbase, y, r.x, v.x * z0);
        scatter_add(accbase, y, r.y, v.y * z1);
        scatter_add(accbase, y, r.z, v.z * z2);
        scatter_add(accbase, y, r.w, v.w * z3);
    }

    // All cluster atomics visible, then flush my 25K rows.
    asm volatile("fence.acq_rel.cluster;" ::: "memory");
    asm volatile("barrier.cluster.arrive.aligned;" ::: "memory");
    asm volatile("barrier.cluster.wait.aligned;" ::: "memory");

    float* yb = y + rank * QN;
    for (int i = tid; i < QN; i += NT) {
        float v = sAcc[i];
        if (v != 0.f) atomicAdd(yb + i, v);
    }
}

extern "C" void kernel_launch(void* const* d_in, const int* in_sizes, int n_in,
                              void* d_out, int out_size) {
    const float* X    = (const float*)d_in[0];
    const int*   rows = (const int*)d_in[1];
    const int*   cols = (const int*)d_in[2];
    const float* vals = (const float*)d_in[3];
    const float* h    = (const float*)d_in[4];
    float* y = (float*)d_out;

    {
        int threads = 256;
        int blocks = (N_NODES + threads - 1) / threads;
        compute_z_kernel<<<blocks, threads>>>(X, h, y);
    }
    {
        static int inited = 0;
        if (!inited) {
            inited = 1;
            cudaFuncSetAttribute(scatter_kernel,
                                 cudaFuncAttributeMaxDynamicSharedMemorySize,
                                 SMEM_TOTAL);
        }
        dim3 grid(CTAS_PER_K, KK);   // 140 CTAs = 70 clusters of 2
        scatter_kernel<<<grid, NT, SMEM_TOTAL>>>(
            (const int4*)rows, (const int4*)cols, (const float4*)vals, y);
    }
}

// round 7
// speedup vs baseline: 2.1402x; 2.1402x over previous
#include <cuda_runtime.h>
#include <cuda_fp16.h>
#include <cstdint>

#define N_NODES 100000
#define HALFN   50000
#define KK 5
#define CC 16
#define EE 3200000
#define PPK (EE / 4)              // 800,000 int4-packs per k
#define NT 1024
#define PAIRS_PER_K 14            // 14 pack-ranges x 2 col-halves = 28 CTAs per k
#define ACC_ROWS 31000
#define ZH_BYTES (HALFN * 2)      // 100,000 B fp16 half-slice
#define ACC_BYTES (ACC_ROWS * 4)  // 124,000 B fp32 accumulator
#define OFF_ACC ZH_BYTES
#define SMEM_TOTAL (ZH_BYTES + ACC_BYTES)   // 224,000 B

__device__ __half g_Zt[KK * N_NODES];

__device__ __forceinline__ uint32_t s2u(const void* p) {
    uint32_t a;
    asm("{ .reg .u64 t; cvta.to.shared.u64 t, %1; cvt.u32.u64 %0, t; }" : "=r"(a) : "l"(p));
    return a;
}

// Kernel 1: Z = X @ h (k-major fp16), zero y (d_out is poisoned).
__global__ __launch_bounds__(256) void compute_z_kernel(
    const float* __restrict__ X, const float* __restrict__ h, float* __restrict__ y)
{
    __shared__ float hs[CC * KK];
    if (threadIdx.x < CC * KK) hs[threadIdx.x] = h[threadIdx.x];
    __syncthreads();
    int n = blockIdx.x * blockDim.x + threadIdx.x;
    if (n >= N_NODES) return;
    float x[CC];
    const float4* xp = reinterpret_cast<const float4*>(X + (size_t)n * CC);
#pragma unroll
    for (int i = 0; i < CC / 4; i++) {
        float4 v = xp[i];
        x[4*i+0]=v.x; x[4*i+1]=v.y; x[4*i+2]=v.z; x[4*i+3]=v.w;
    }
#pragma unroll
    for (int k = 0; k < KK; k++) {
        float acc = 0.f;
#pragma unroll
        for (int c = 0; c < CC; c++) acc += x[c] * hs[c * KK + k];
        g_Zt[k * N_NODES + n] = __float2half_rn(acc);
    }
    y[n] = 0.f;
}

// Predicated gather from the local fp16 half-slice (no branch).
__device__ __forceinline__ float gather_half(uint32_t zbase, uint32_t cl) {
    uint32_t za = zbase + (cl < (uint32_t)HALFN ? cl * 2u : 0u);
    unsigned short hb;
    asm volatile(
        "{\n\t.reg .pred p;\n\t"
        "setp.lt.u32 p, %1, 50000;\n\t"
        "@p  ld.shared.u16 %0, [%2];\n\t"
        "@!p mov.u16 %0, 0;\n\t}"
        : "=h"(hb) : "r"(cl), "r"(za));
    return __half2float(__ushort_as_half(hb));
}

// Predicated dual-pipe scatter: smem window -> ATOMS, else -> REDG. No branch.
__device__ __forceinline__ void scatter_dual(uint32_t accbase, float* __restrict__ y,
                                             uint32_t cl, int r, uint32_t acc_start, float s) {
    uint32_t lr = (uint32_t)r - acc_start;            // unsigned wrap: in-window iff < ACC_ROWS
    uint32_t sa = accbase + (lr < (uint32_t)ACC_ROWS ? lr * 4u : 0u);
    asm volatile(
        "{\n\t.reg .pred pa, ps, pg;\n\t"
        "setp.lt.u32 pa, %0, 50000;\n\t"     // edge belongs to this CTA's col-half
        "setp.lt.u32 ps, %1, 31000;\n\t"     // row in smem window
        "and.pred ps, ps, pa;\n\t"
        "not.pred pg, ps;\n\t"
        "and.pred pg, pg, pa;\n\t"
        "@ps red.shared::cta.add.f32 [%2], %4;\n\t"
        "@pg red.global.add.f32 [%3], %4;\n\t}"
        :: "r"(cl), "r"(lr), "r"(sa), "l"(y + r), "f"(s) : "memory");
}

// Kernel 2: col-partitioned dual-pipe scatter. 28 CTAs per k (14 ranges x 2 halves).
__global__ __launch_bounds__(NT, 1)
void scatter_kernel(const int4* __restrict__ rows, const int4* __restrict__ cols,
                    const float4* __restrict__ vals, float* __restrict__ y)
{
    extern __shared__ __align__(16) char smem[];
    __half* sZ   = reinterpret_cast<__half*>(smem);
    float*  sAcc = reinterpret_cast<float*>(smem + OFF_ACC);
    const uint32_t zbase   = s2u(smem);
    const uint32_t accbase = zbase + OFF_ACC;
    const int tid = threadIdx.x;

    const int xx   = blockIdx.x;          // 0..27 ; pair = xx>>1, half = xx&1
    const int k    = blockIdx.y;
    const int pair = xx >> 1;
    const int half = xx & 1;
    const int cta_id = k * (2 * PAIRS_PER_K) + xx;
    const uint32_t acc_start = (uint32_t)(((long long)cta_id * 7321) % (N_NODES - ACC_ROWS + 1));
    const int half_off = half * HALFN;

    // Stage my fp16 half-slice + zero accumulator.
    {
        const int4* src = reinterpret_cast<const int4*>(g_Zt + (size_t)k * N_NODES + half_off);
        int4* dst = reinterpret_cast<int4*>(sZ);
        for (int i = tid; i < ZH_BYTES / 16; i += NT) dst[i] = src[i];
        float4* a4 = reinterpret_cast<float4*>(sAcc);
        float4 z4 = make_float4(0.f, 0.f, 0.f, 0.f);
        for (int i = tid; i < ACC_BYTES / 16; i += NT) a4[i] = z4;
    }
    __syncthreads();

    // Pack range shared by both col-half CTAs of this pair (adjacent blockIdx.x
    // -> concurrent -> the duplicate stream read hits L2, not DRAM).
    int p   = k * PPK + (int)(((long long)pair * PPK) / PAIRS_PER_K);
    int end = k * PPK + (int)(((long long)(pair + 1) * PPK) / PAIRS_PER_K);

    for (int q = p + tid; q < end; q += NT) {
        int4   r = __ldcg(rows + q);
        int4   c = __ldcg(cols + q);
        float4 v = __ldcg(vals + q);

        uint32_t c0 = (uint32_t)(c.x - half_off);
        uint32_t c1 = (uint32_t)(c.y - half_off);
        uint32_t c2 = (uint32_t)(c.z - half_off);
        uint32_t c3 = (uint32_t)(c.w - half_off);

        float z0 = gather_half(zbase, c0);
        float z1 = gather_half(zbase, c1);
        float z2 = gather_half(zbase, c2);
        float z3 = gather_half(zbase, c3);

        scatter_dual(accbase, y, c0, r.x, acc_start, v.x * z0);
        scatter_dual(accbase, y, c1, r.y, acc_start, v.y * z1);
        scatter_dual(accbase, y, c2, r.z, acc_start, v.z * z2);
        scatter_dual(accbase, y, c3, r.w, acc_start, v.w * z3);
    }

    // Flush accumulator window (coalesced global adds).
    __syncthreads();
    float* yb = y + acc_start;
    for (int i = tid; i < ACC_ROWS; i += NT)
        atomicAdd(yb + i, sAcc[i]);
}

extern "C" void kernel_launch(void* const* d_in, const int* in_sizes, int n_in,
                              void* d_out, int out_size) {
    const float* X    = (const float*)d_in[0];
    const int*   rows = (const int*)d_in[1];
    const int*   cols = (const int*)d_in[2];
    const float* vals = (const float*)d_in[3];
    const float* h    = (const float*)d_in[4];
    float* y = (float*)d_out;

    {
        int threads = 256;
        int blocks = (N_NODES + threads - 1) / threads;
        compute_z_kernel<<<blocks, threads>>>(X, h, y);
    }
    {
        static int inited = 0;
        if (!inited) {
            inited = 1;
            cudaFuncSetAttribute(scatter_kernel,
                                 cudaFuncAttributeMaxDynamicSharedMemorySize,
                                 SMEM_TOTAL);
        }
        dim3 grid(2 * PAIRS_PER_K, KK);    // (28, 5) = 140 CTAs
        scatter_kernel<<<grid, NT, SMEM_TOTAL>>>(
            (const int4*)rows, (const int4*)cols, (const float4*)vals, y);
    }
}